// round 1
// baseline (speedup 1.0000x reference)
#include <cuda_runtime.h>
#include <math.h>

// Problem constants
#define B_N   16
#define RES_N 32
#define N_TOK 1024
#define DIM_N 768
#define H_N   12
#define KD_N  64
#define QKVD  2304          // 3*H*KD
#define MROWS (B_N * N_TOK) // 16384
#define SCALE_C 0.125f      // KD^-0.5
#define LN_EPS  1e-5f

// Scratch (device globals — no dynamic allocation allowed)
__device__ float g_xn[(size_t)MROWS * DIM_N];    // 50 MB
__device__ float g_qkv[(size_t)MROWS * QKVD];    // 151 MB
__device__ float g_att[(size_t)MROWS * DIM_N];   // 50 MB

// ---------------------------------------------------------------------------
// Kernel 1: LayerNorm. One block per (b,n) row of 768. 256 threads.
// ---------------------------------------------------------------------------
__global__ void ln_kernel(const float* __restrict__ x,
                          const float* __restrict__ w,
                          const float* __restrict__ b) {
    int row = blockIdx.x;
    const float* xr = x + (size_t)row * DIM_N;
    int t = threadIdx.x;
    float v0 = xr[t], v1 = xr[t + 256], v2 = xr[t + 512];
    float s  = v0 + v1 + v2;
    float sq = v0 * v0 + v1 * v1 + v2 * v2;
    #pragma unroll
    for (int o = 16; o; o >>= 1) {
        s  += __shfl_xor_sync(0xffffffffu, s, o);
        sq += __shfl_xor_sync(0xffffffffu, sq, o);
    }
    __shared__ float ss[8], ssq[8];
    int wid = t >> 5, lid = t & 31;
    if (lid == 0) { ss[wid] = s; ssq[wid] = sq; }
    __syncthreads();
    if (wid == 0) {
        s = ss[lid & 7]; sq = ssq[lid & 7];
        #pragma unroll
        for (int o = 4; o; o >>= 1) {
            s  += __shfl_xor_sync(0xffffffffu, s, o);
            sq += __shfl_xor_sync(0xffffffffu, sq, o);
        }
        if (lid == 0) { ss[0] = s; ssq[0] = sq; }
    }
    __syncthreads();
    float mean = ss[0] * (1.0f / DIM_N);
    float var  = ssq[0] * (1.0f / DIM_N) - mean * mean;
    float rstd = rsqrtf(var + LN_EPS);
    float* o = g_xn + (size_t)row * DIM_N;
    int c = t;
    o[c] = (v0 - mean) * rstd * w[c] + b[c]; c += 256;
    o[c] = (v1 - mean) * rstd * w[c] + b[c]; c += 256;
    o[c] = (v2 - mean) * rstd * w[c] + b[c];
}

// ---------------------------------------------------------------------------
// Kernel 2/4: SGEMM  C[M,J] = A[M,K] @ W[J,K]^T + bias[J]
// 128x128 block tile, BK=8, 256 threads, 8x8 microtile, prefetched loads.
// M, J multiples of 128; K multiple of 8.
// ---------------------------------------------------------------------------
__global__ void __launch_bounds__(256, 2)
sgemm_bias(const float* __restrict__ A, const float* __restrict__ W,
           const float* __restrict__ bias, float* __restrict__ C,
           int M, int J, int K) {
    __shared__ float Ash[8][128];
    __shared__ float Wsh[8][128];
    int m0 = blockIdx.y * 128;
    int j0 = blockIdx.x * 128;
    int tid = threadIdx.x;
    int tx = tid & 15, ty = tid >> 4;

    int lr = tid >> 1;        // 0..127
    int lc = (tid & 1) * 4;   // 0 or 4
    const float* Ap = A + (size_t)(m0 + lr) * K + lc;
    const float* Wp = W + (size_t)(j0 + lr) * K + lc;

    float acc[8][8];
    #pragma unroll
    for (int i = 0; i < 8; i++)
        #pragma unroll
        for (int j = 0; j < 8; j++) acc[i][j] = 0.0f;

    float4 av = *(const float4*)(Ap);
    float4 wv = *(const float4*)(Wp);

    for (int k0 = 0; k0 < K; k0 += 8) {
        Ash[lc + 0][lr] = av.x; Ash[lc + 1][lr] = av.y;
        Ash[lc + 2][lr] = av.z; Ash[lc + 3][lr] = av.w;
        Wsh[lc + 0][lr] = wv.x; Wsh[lc + 1][lr] = wv.y;
        Wsh[lc + 2][lr] = wv.z; Wsh[lc + 3][lr] = wv.w;
        __syncthreads();
        if (k0 + 8 < K) {
            av = *(const float4*)(Ap + k0 + 8);
            wv = *(const float4*)(Wp + k0 + 8);
        }
        #pragma unroll
        for (int kk = 0; kk < 8; kk++) {
            float a[8], w[8];
            *(float4*)(a)     = *(const float4*)&Ash[kk][ty * 8];
            *(float4*)(a + 4) = *(const float4*)&Ash[kk][ty * 8 + 4];
            *(float4*)(w)     = *(const float4*)&Wsh[kk][tx * 8];
            *(float4*)(w + 4) = *(const float4*)&Wsh[kk][tx * 8 + 4];
            #pragma unroll
            for (int i = 0; i < 8; i++)
                #pragma unroll
                for (int j = 0; j < 8; j++)
                    acc[i][j] = fmaf(a[i], w[j], acc[i][j]);
        }
        __syncthreads();
    }

    float bb[8];
    #pragma unroll
    for (int j = 0; j < 8; j++) bb[j] = bias[j0 + tx * 8 + j];
    #pragma unroll
    for (int i = 0; i < 8; i++) {
        float* Cr = C + (size_t)(m0 + ty * 8 + i) * J + j0 + tx * 8;
        #pragma unroll
        for (int j = 0; j < 8; j++) Cr[j] = acc[i][j] + bb[j];
    }
}

// ---------------------------------------------------------------------------
// Kernel 3: fused flash-style attention.
// Block = (query-tile 64, head, batch). 256 threads (16x16).
// smem: q[64][65], k[64][65], v[64][65], p[64][65], bias[1024]  = 70656 B
// Thread (tx,ty): S rows qi = ty*4+i, cols m = tx + j*16 (conflict-free);
// PV: out rows qi, dims d = tx + j*16.
// Bias computed analytically: idx = |yq-ym|*32 + |xq-xm|.
// ---------------------------------------------------------------------------
__global__ void __launch_bounds__(256, 2)
attn_kernel(const float* __restrict__ biases) {
    extern __shared__ float sm[];
    float* q_s = sm;                 // 64*65
    float* k_s = q_s + 64 * 65;
    float* v_s = k_s + 64 * 65;
    float* p_s = v_s + 64 * 65;
    float* b_s = p_s + 64 * 65;      // 1024

    int qt = blockIdx.x, h = blockIdx.y, b = blockIdx.z;
    int tid = threadIdx.x;
    int n0 = qt * 64;

    for (int i = tid; i < 1024; i += 256) b_s[i] = biases[h * 1024 + i];

    // Load Q tile [64][64]
    {
        int r = tid >> 2, c0 = (tid & 3) * 16;
        const float* qp = g_qkv + (size_t)(b * N_TOK + n0 + r) * QKVD + h * 192;
        #pragma unroll
        for (int c = 0; c < 16; c += 4) {
            float4 v = *(const float4*)(qp + c0 + c);
            q_s[r * 65 + c0 + c + 0] = v.x;
            q_s[r * 65 + c0 + c + 1] = v.y;
            q_s[r * 65 + c0 + c + 2] = v.z;
            q_s[r * 65 + c0 + c + 3] = v.w;
        }
    }
    __syncthreads();

    int tx = tid & 15, ty = tid >> 4;
    float acc[4][4];
    float m_i[4], l_i[4];
    #pragma unroll
    for (int i = 0; i < 4; i++) {
        m_i[i] = -1e30f; l_i[i] = 0.0f;
        #pragma unroll
        for (int j = 0; j < 4; j++) acc[i][j] = 0.0f;
    }

    int nq[4], yq[4], xq[4];
    #pragma unroll
    for (int i = 0; i < 4; i++) {
        nq[i] = n0 + ty * 4 + i;
        yq[i] = nq[i] >> 5;
        xq[i] = nq[i] & 31;
    }

    for (int kt = 0; kt < 16; kt++) {
        // Load K,V tiles
        {
            int r = tid >> 2, c0 = (tid & 3) * 16;
            const float* kp = g_qkv + (size_t)(b * N_TOK + kt * 64 + r) * QKVD
                              + h * 192 + 64;
            const float* vp = kp + 64;
            #pragma unroll
            for (int c = 0; c < 16; c += 4) {
                float4 kv = *(const float4*)(kp + c0 + c);
                k_s[r * 65 + c0 + c + 0] = kv.x;
                k_s[r * 65 + c0 + c + 1] = kv.y;
                k_s[r * 65 + c0 + c + 2] = kv.z;
                k_s[r * 65 + c0 + c + 3] = kv.w;
                float4 vv = *(const float4*)(vp + c0 + c);
                v_s[r * 65 + c0 + c + 0] = vv.x;
                v_s[r * 65 + c0 + c + 1] = vv.y;
                v_s[r * 65 + c0 + c + 2] = vv.z;
                v_s[r * 65 + c0 + c + 3] = vv.w;
            }
        }
        __syncthreads();

        // S = Q @ K^T  (4x4 microtile, m = tx + j*16)
        float s[4][4];
        #pragma unroll
        for (int i = 0; i < 4; i++)
            #pragma unroll
            for (int j = 0; j < 4; j++) s[i][j] = 0.0f;
        #pragma unroll 8
        for (int d = 0; d < 64; d++) {
            float qa[4], kb[4];
            #pragma unroll
            for (int i = 0; i < 4; i++) qa[i] = q_s[(ty * 4 + i) * 65 + d];
            #pragma unroll
            for (int j = 0; j < 4; j++) kb[j] = k_s[(tx + j * 16) * 65 + d];
            #pragma unroll
            for (int i = 0; i < 4; i++)
                #pragma unroll
                for (int j = 0; j < 4; j++)
                    s[i][j] = fmaf(qa[i], kb[j], s[i][j]);
        }

        // scale + relative-position bias (computed analytically)
        #pragma unroll
        for (int i = 0; i < 4; i++) {
            #pragma unroll
            for (int j = 0; j < 4; j++) {
                int nm = kt * 64 + tx + j * 16;
                int dy = abs(yq[i] - (nm >> 5));
                int dx = abs(xq[i] - (nm & 31));
                s[i][j] = s[i][j] * SCALE_C + b_s[dy * 32 + dx];
            }
        }

        // Online softmax per query row (reduce across the 16 tx lanes)
        #pragma unroll
        for (int i = 0; i < 4; i++) {
            float mx = fmaxf(fmaxf(s[i][0], s[i][1]), fmaxf(s[i][2], s[i][3]));
            #pragma unroll
            for (int o = 8; o; o >>= 1)
                mx = fmaxf(mx, __shfl_xor_sync(0xffffffffu, mx, o));
            float mnew = fmaxf(m_i[i], mx);
            float corr = __expf(m_i[i] - mnew);
            float rs = 0.0f;
            #pragma unroll
            for (int j = 0; j < 4; j++) {
                float p = __expf(s[i][j] - mnew);
                p_s[(ty * 4 + i) * 65 + tx + j * 16] = p;
                rs += p;
            }
            #pragma unroll
            for (int o = 8; o; o >>= 1)
                rs += __shfl_xor_sync(0xffffffffu, rs, o);
            l_i[i] = l_i[i] * corr + rs;
            m_i[i] = mnew;
            #pragma unroll
            for (int j = 0; j < 4; j++) acc[i][j] *= corr;
        }
        __syncthreads();

        // acc += P @ V   (dims d = tx + j*16)
        #pragma unroll 8
        for (int m = 0; m < 64; m++) {
            float pr[4], vr[4];
            #pragma unroll
            for (int i = 0; i < 4; i++) pr[i] = p_s[(ty * 4 + i) * 65 + m];
            #pragma unroll
            for (int j = 0; j < 4; j++) vr[j] = v_s[m * 65 + tx + j * 16];
            #pragma unroll
            for (int i = 0; i < 4; i++)
                #pragma unroll
                for (int j = 0; j < 4; j++)
                    acc[i][j] = fmaf(pr[i], vr[j], acc[i][j]);
        }
        __syncthreads();
    }

    // Epilogue: normalize and store to g_att[b,n, h*64 + d]
    #pragma unroll
    for (int i = 0; i < 4; i++) {
        float inv = 1.0f / l_i[i];
        float* op = g_att + (size_t)(b * N_TOK + n0 + ty * 4 + i) * DIM_N
                    + h * 64;
        #pragma unroll
        for (int j = 0; j < 4; j++)
            op[tx + j * 16] = acc[i][j] * inv;
    }
}

// ---------------------------------------------------------------------------
extern "C" void kernel_launch(void* const* d_in, const int* in_sizes, int n_in,
                              void* d_out, int out_size) {
    const float* x           = (const float*)d_in[0];
    const float* ln_w        = (const float*)d_in[1];
    const float* ln_b        = (const float*)d_in[2];
    const float* qkv_w       = (const float*)d_in[3];
    const float* qkv_b       = (const float*)d_in[4];
    const float* proj_w      = (const float*)d_in[5];
    const float* proj_b      = (const float*)d_in[6];
    const float* attn_biases = (const float*)d_in[7];
    // d_in[8] = bias_idxs: unused (indices recomputed analytically in-kernel)
    float* out = (float*)d_out;

    void *p_xn, *p_qkv, *p_att;
    cudaGetSymbolAddress(&p_xn, g_xn);
    cudaGetSymbolAddress(&p_qkv, g_qkv);
    cudaGetSymbolAddress(&p_att, g_att);

    const int ATTN_SMEM = (4 * 64 * 65 + 1024) * 4; // 70656 B
    cudaFuncSetAttribute(attn_kernel,
                         cudaFuncAttributeMaxDynamicSharedMemorySize, ATTN_SMEM);

    // 1. LayerNorm
    ln_kernel<<<MROWS, 256>>>(x, ln_w, ln_b);

    // 2. QKV GEMM: [16384,768] @ [2304,768]^T -> [16384,2304]
    sgemm_bias<<<dim3(QKVD / 128, MROWS / 128), 256>>>(
        (const float*)p_xn, qkv_w, qkv_b, (float*)p_qkv, MROWS, QKVD, DIM_N);

    // 3. Fused attention
    attn_kernel<<<dim3(N_TOK / 64, H_N, B_N), 256, ATTN_SMEM>>>(attn_biases);

    // 4. Projection GEMM: [16384,768] @ [768,768]^T -> out
    sgemm_bias<<<dim3(DIM_N / 128, MROWS / 128), 256>>>(
        (const float*)p_att, proj_w, proj_b, out, MROWS, DIM_N, DIM_N);
}

// round 2
// speedup vs baseline: 1.4918x; 1.4918x over previous
#include <cuda_runtime.h>
#include <math.h>
#include <stdint.h>

// Problem constants
#define B_N   16
#define RES_N 32
#define N_TOK 1024
#define DIM_N 768
#define H_N   12
#define KD_N  64
#define QKVD  2304          // 3*H*KD
#define MROWS (B_N * N_TOK) // 16384
#define SCALE_C 0.125f      // KD^-0.5
#define LN_EPS  1e-5f
#define TS 36               // smem row stride (floats) — conflict-free frag gathers

// Scratch (device globals — no dynamic allocation allowed)
__device__ float g_xn[(size_t)MROWS * DIM_N];    // 50 MB
__device__ float g_qkv[(size_t)MROWS * QKVD];    // 151 MB
__device__ float g_att[(size_t)MROWS * DIM_N];   // 50 MB

__device__ __forceinline__ float t32(float x) {
    asm("cvt.rna.tf32.f32 %0, %0;" : "+f"(x));
    return x;
}

__device__ __forceinline__ void mma_tf32(float* c, const uint32_t* a,
                                         const uint32_t* b) {
    asm volatile(
        "mma.sync.aligned.m16n8k8.row.col.f32.tf32.tf32.f32 "
        "{%0,%1,%2,%3}, {%4,%5,%6,%7}, {%8,%9}, {%0,%1,%2,%3};"
        : "+f"(c[0]), "+f"(c[1]), "+f"(c[2]), "+f"(c[3])
        : "r"(a[0]), "r"(a[1]), "r"(a[2]), "r"(a[3]), "r"(b[0]), "r"(b[1]));
}

// ---------------------------------------------------------------------------
// Kernel 1: LayerNorm. One block per (b,n) row of 768. 256 threads.
// ---------------------------------------------------------------------------
__global__ void ln_kernel(const float* __restrict__ x,
                          const float* __restrict__ w,
                          const float* __restrict__ b) {
    int row = blockIdx.x;
    const float* xr = x + (size_t)row * DIM_N;
    int t = threadIdx.x;
    float v0 = xr[t], v1 = xr[t + 256], v2 = xr[t + 512];
    float s  = v0 + v1 + v2;
    float sq = v0 * v0 + v1 * v1 + v2 * v2;
    #pragma unroll
    for (int o = 16; o; o >>= 1) {
        s  += __shfl_xor_sync(0xffffffffu, s, o);
        sq += __shfl_xor_sync(0xffffffffu, sq, o);
    }
    __shared__ float ss[8], ssq[8];
    int wid = t >> 5, lid = t & 31;
    if (lid == 0) { ss[wid] = s; ssq[wid] = sq; }
    __syncthreads();
    if (wid == 0) {
        s = ss[lid & 7]; sq = ssq[lid & 7];
        #pragma unroll
        for (int o = 4; o; o >>= 1) {
            s  += __shfl_xor_sync(0xffffffffu, s, o);
            sq += __shfl_xor_sync(0xffffffffu, sq, o);
        }
        if (lid == 0) { ss[0] = s; ssq[0] = sq; }
    }
    __syncthreads();
    float mean = ss[0] * (1.0f / DIM_N);
    float var  = ssq[0] * (1.0f / DIM_N) - mean * mean;
    float rstd = rsqrtf(var + LN_EPS);
    float* o = g_xn + (size_t)row * DIM_N;
    int c = t;
    o[c] = (v0 - mean) * rstd * w[c] + b[c]; c += 256;
    o[c] = (v1 - mean) * rstd * w[c] + b[c]; c += 256;
    o[c] = (v2 - mean) * rstd * w[c] + b[c];
}

// ---------------------------------------------------------------------------
// Kernel 2/4: TF32 tensor-core GEMM  C[M,J] = A[M,K] @ W[J,K]^T + bias[J]
// 128x128 block tile, BK=32, 256 threads = 8 warps (2m x 4n), warp tile 64x32,
// mma.sync.m16n8k8.tf32. Smem stride 36 -> conflict-free fragment gathers.
// ---------------------------------------------------------------------------
__global__ void __launch_bounds__(256)
tgemm_bias(const float* __restrict__ A, const float* __restrict__ W,
           const float* __restrict__ bias, float* __restrict__ C,
           int M, int J, int K) {
    __shared__ float Ash[128 * TS];
    __shared__ float Wsh[128 * TS];
    int m0 = blockIdx.y * 128;
    int j0 = blockIdx.x * 128;
    int tid = threadIdx.x;
    int warp = tid >> 5, lane = tid & 31;
    int gid = lane >> 2, tig = lane & 3;
    int wm = (warp >> 2) * 64;   // 0 or 64
    int wn = (warp & 3) * 32;    // 0,32,64,96
    int lr = tid >> 1;           // 0..127
    int lc = (tid & 1) * 16;     // 0 or 16

    const float* Ap = A + (size_t)(m0 + lr) * K + lc;
    const float* Wp = W + (size_t)(j0 + lr) * K + lc;

    float acc[4][4][4];
    #pragma unroll
    for (int mt = 0; mt < 4; mt++)
        #pragma unroll
        for (int nt = 0; nt < 4; nt++)
            #pragma unroll
            for (int e = 0; e < 4; e++) acc[mt][nt][e] = 0.0f;

    float4 pa[4], pw[4];
    #pragma unroll
    for (int c = 0; c < 4; c++) {
        pa[c] = *(const float4*)(Ap + 4 * c);
        pw[c] = *(const float4*)(Wp + 4 * c);
    }

    for (int k0 = 0; k0 < K; k0 += 32) {
        float* As = &Ash[lr * TS + lc];
        float* Ws = &Wsh[lr * TS + lc];
        #pragma unroll
        for (int c = 0; c < 4; c++) {
            As[4 * c + 0] = t32(pa[c].x); As[4 * c + 1] = t32(pa[c].y);
            As[4 * c + 2] = t32(pa[c].z); As[4 * c + 3] = t32(pa[c].w);
            Ws[4 * c + 0] = t32(pw[c].x); Ws[4 * c + 1] = t32(pw[c].y);
            Ws[4 * c + 2] = t32(pw[c].z); Ws[4 * c + 3] = t32(pw[c].w);
        }
        __syncthreads();
        if (k0 + 32 < K) {
            #pragma unroll
            for (int c = 0; c < 4; c++) {
                pa[c] = *(const float4*)(Ap + k0 + 32 + 4 * c);
                pw[c] = *(const float4*)(Wp + k0 + 32 + 4 * c);
            }
        }
        const uint32_t* Au = (const uint32_t*)Ash;
        const uint32_t* Wu = (const uint32_t*)Wsh;
        #pragma unroll
        for (int ks = 0; ks < 4; ks++) {
            uint32_t af[4][4], bf[4][2];
            #pragma unroll
            for (int mt = 0; mt < 4; mt++) {
                int r = (wm + mt * 16 + gid) * TS + ks * 8 + tig;
                af[mt][0] = Au[r];
                af[mt][1] = Au[r + 8 * TS];
                af[mt][2] = Au[r + 4];
                af[mt][3] = Au[r + 8 * TS + 4];
            }
            #pragma unroll
            for (int nt = 0; nt < 4; nt++) {
                int r = (wn + nt * 8 + gid) * TS + ks * 8 + tig;
                bf[nt][0] = Wu[r];
                bf[nt][1] = Wu[r + 4];
            }
            #pragma unroll
            for (int mt = 0; mt < 4; mt++)
                #pragma unroll
                for (int nt = 0; nt < 4; nt++)
                    mma_tf32(acc[mt][nt], af[mt], bf[nt]);
        }
        __syncthreads();
    }

    // Epilogue
    #pragma unroll
    for (int mt = 0; mt < 4; mt++) {
        int row0 = m0 + wm + mt * 16 + gid;
        #pragma unroll
        for (int nt = 0; nt < 4; nt++) {
            int col = j0 + wn + nt * 8 + tig * 2;
            float b0 = bias[col], b1 = bias[col + 1];
            float2 v0 = make_float2(acc[mt][nt][0] + b0, acc[mt][nt][1] + b1);
            float2 v1 = make_float2(acc[mt][nt][2] + b0, acc[mt][nt][3] + b1);
            *(float2*)&C[(size_t)row0 * J + col] = v0;
            *(float2*)&C[(size_t)(row0 + 8) * J + col] = v1;
        }
    }
}

// ---------------------------------------------------------------------------
// Kernel 3: fused flash-style attention (unchanged from R1).
// ---------------------------------------------------------------------------
__global__ void __launch_bounds__(256, 2)
attn_kernel(const float* __restrict__ biases) {
    extern __shared__ float sm[];
    float* q_s = sm;                 // 64*65
    float* k_s = q_s + 64 * 65;
    float* v_s = k_s + 64 * 65;
    float* p_s = v_s + 64 * 65;
    float* b_s = p_s + 64 * 65;      // 1024

    int qt = blockIdx.x, h = blockIdx.y, b = blockIdx.z;
    int tid = threadIdx.x;
    int n0 = qt * 64;

    for (int i = tid; i < 1024; i += 256) b_s[i] = biases[h * 1024 + i];

    {
        int r = tid >> 2, c0 = (tid & 3) * 16;
        const float* qp = g_qkv + (size_t)(b * N_TOK + n0 + r) * QKVD + h * 192;
        #pragma unroll
        for (int c = 0; c < 16; c += 4) {
            float4 v = *(const float4*)(qp + c0 + c);
            q_s[r * 65 + c0 + c + 0] = v.x;
            q_s[r * 65 + c0 + c + 1] = v.y;
            q_s[r * 65 + c0 + c + 2] = v.z;
            q_s[r * 65 + c0 + c + 3] = v.w;
        }
    }
    __syncthreads();

    int tx = tid & 15, ty = tid >> 4;
    float acc[4][4];
    float m_i[4], l_i[4];
    #pragma unroll
    for (int i = 0; i < 4; i++) {
        m_i[i] = -1e30f; l_i[i] = 0.0f;
        #pragma unroll
        for (int j = 0; j < 4; j++) acc[i][j] = 0.0f;
    }

    int nq[4], yq[4], xq[4];
    #pragma unroll
    for (int i = 0; i < 4; i++) {
        nq[i] = n0 + ty * 4 + i;
        yq[i] = nq[i] >> 5;
        xq[i] = nq[i] & 31;
    }

    for (int kt = 0; kt < 16; kt++) {
        {
            int r = tid >> 2, c0 = (tid & 3) * 16;
            const float* kp = g_qkv + (size_t)(b * N_TOK + kt * 64 + r) * QKVD
                              + h * 192 + 64;
            const float* vp = kp + 64;
            #pragma unroll
            for (int c = 0; c < 16; c += 4) {
                float4 kv = *(const float4*)(kp + c0 + c);
                k_s[r * 65 + c0 + c + 0] = kv.x;
                k_s[r * 65 + c0 + c + 1] = kv.y;
                k_s[r * 65 + c0 + c + 2] = kv.z;
                k_s[r * 65 + c0 + c + 3] = kv.w;
                float4 vv = *(const float4*)(vp + c0 + c);
                v_s[r * 65 + c0 + c + 0] = vv.x;
                v_s[r * 65 + c0 + c + 1] = vv.y;
                v_s[r * 65 + c0 + c + 2] = vv.z;
                v_s[r * 65 + c0 + c + 3] = vv.w;
            }
        }
        __syncthreads();

        float s[4][4];
        #pragma unroll
        for (int i = 0; i < 4; i++)
            #pragma unroll
            for (int j = 0; j < 4; j++) s[i][j] = 0.0f;
        #pragma unroll 8
        for (int d = 0; d < 64; d++) {
            float qa[4], kb[4];
            #pragma unroll
            for (int i = 0; i < 4; i++) qa[i] = q_s[(ty * 4 + i) * 65 + d];
            #pragma unroll
            for (int j = 0; j < 4; j++) kb[j] = k_s[(tx + j * 16) * 65 + d];
            #pragma unroll
            for (int i = 0; i < 4; i++)
                #pragma unroll
                for (int j = 0; j < 4; j++)
                    s[i][j] = fmaf(qa[i], kb[j], s[i][j]);
        }

        #pragma unroll
        for (int i = 0; i < 4; i++) {
            #pragma unroll
            for (int j = 0; j < 4; j++) {
                int nm = kt * 64 + tx + j * 16;
                int dy = abs(yq[i] - (nm >> 5));
                int dx = abs(xq[i] - (nm & 31));
                s[i][j] = s[i][j] * SCALE_C + b_s[dy * 32 + dx];
            }
        }

        #pragma unroll
        for (int i = 0; i < 4; i++) {
            float mx = fmaxf(fmaxf(s[i][0], s[i][1]), fmaxf(s[i][2], s[i][3]));
            #pragma unroll
            for (int o = 8; o; o >>= 1)
                mx = fmaxf(mx, __shfl_xor_sync(0xffffffffu, mx, o));
            float mnew = fmaxf(m_i[i], mx);
            float corr = __expf(m_i[i] - mnew);
            float rs = 0.0f;
            #pragma unroll
            for (int j = 0; j < 4; j++) {
                float p = __expf(s[i][j] - mnew);
                p_s[(ty * 4 + i) * 65 + tx + j * 16] = p;
                rs += p;
            }
            #pragma unroll
            for (int o = 8; o; o >>= 1)
                rs += __shfl_xor_sync(0xffffffffu, rs, o);
            l_i[i] = l_i[i] * corr + rs;
            m_i[i] = mnew;
            #pragma unroll
            for (int j = 0; j < 4; j++) acc[i][j] *= corr;
        }
        __syncthreads();

        #pragma unroll 8
        for (int m = 0; m < 64; m++) {
            float pr[4], vr[4];
            #pragma unroll
            for (int i = 0; i < 4; i++) pr[i] = p_s[(ty * 4 + i) * 65 + m];
            #pragma unroll
            for (int j = 0; j < 4; j++) vr[j] = v_s[m * 65 + tx + j * 16];
            #pragma unroll
            for (int i = 0; i < 4; i++)
                #pragma unroll
                for (int j = 0; j < 4; j++)
                    acc[i][j] = fmaf(pr[i], vr[j], acc[i][j]);
        }
        __syncthreads();
    }

    #pragma unroll
    for (int i = 0; i < 4; i++) {
        float inv = 1.0f / l_i[i];
        float* op = g_att + (size_t)(b * N_TOK + n0 + ty * 4 + i) * DIM_N
                    + h * 64;
        #pragma unroll
        for (int j = 0; j < 4; j++)
            op[tx + j * 16] = acc[i][j] * inv;
    }
}

// ---------------------------------------------------------------------------
extern "C" void kernel_launch(void* const* d_in, const int* in_sizes, int n_in,
                              void* d_out, int out_size) {
    const float* x           = (const float*)d_in[0];
    const float* ln_w        = (const float*)d_in[1];
    const float* ln_b        = (const float*)d_in[2];
    const float* qkv_w       = (const float*)d_in[3];
    const float* qkv_b       = (const float*)d_in[4];
    const float* proj_w      = (const float*)d_in[5];
    const float* proj_b      = (const float*)d_in[6];
    const float* attn_biases = (const float*)d_in[7];
    // d_in[8] = bias_idxs: unused (indices recomputed analytically in-kernel)
    float* out = (float*)d_out;

    void *p_xn, *p_qkv, *p_att;
    cudaGetSymbolAddress(&p_xn, g_xn);
    cudaGetSymbolAddress(&p_qkv, g_qkv);
    cudaGetSymbolAddress(&p_att, g_att);

    const int ATTN_SMEM = (4 * 64 * 65 + 1024) * 4; // 70656 B
    cudaFuncSetAttribute(attn_kernel,
                         cudaFuncAttributeMaxDynamicSharedMemorySize, ATTN_SMEM);

    // 1. LayerNorm
    ln_kernel<<<MROWS, 256>>>(x, ln_w, ln_b);

    // 2. QKV GEMM (TF32 tensor cores): [16384,768] @ [2304,768]^T
    tgemm_bias<<<dim3(QKVD / 128, MROWS / 128), 256>>>(
        (const float*)p_xn, qkv_w, qkv_b, (float*)p_qkv, MROWS, QKVD, DIM_N);

    // 3. Fused attention
    attn_kernel<<<dim3(N_TOK / 64, H_N, B_N), 256, ATTN_SMEM>>>(attn_biases);

    // 4. Projection GEMM (TF32 tensor cores): [16384,768] @ [768,768]^T
    tgemm_bias<<<dim3(DIM_N / 128, MROWS / 128), 256>>>(
        (const float*)p_att, proj_w, proj_b, out, MROWS, DIM_N, DIM_N);
}

// round 3
// speedup vs baseline: 2.0696x; 1.3873x over previous
#include <cuda_runtime.h>
#include <math.h>
#include <stdint.h>

// Problem constants
#define B_N   16
#define RES_N 32
#define N_TOK 1024
#define DIM_N 768
#define H_N   12
#define KD_N  64
#define QKVD  2304          // 3*H*KD
#define MROWS (B_N * N_TOK) // 16384
#define SCALE_C 0.125f      // KD^-0.5
#define LN_EPS  1e-5f
#define TS 36               // GEMM smem row stride
#define ST 68               // attention smem row stride (conflict-free frags)

// Scratch (device globals — no dynamic allocation allowed)
__device__ float g_xn[(size_t)MROWS * DIM_N];
__device__ float g_qkv[(size_t)MROWS * QKVD];
__device__ float g_att[(size_t)MROWS * DIM_N];

__device__ __forceinline__ float t32(float x) {
    asm("cvt.rna.tf32.f32 %0, %0;" : "+f"(x));
    return x;
}

__device__ __forceinline__ void mma_tf32(float* c, const uint32_t* a,
                                         const uint32_t* b) {
    asm volatile(
        "mma.sync.aligned.m16n8k8.row.col.f32.tf32.tf32.f32 "
        "{%0,%1,%2,%3}, {%4,%5,%6,%7}, {%8,%9}, {%0,%1,%2,%3};"
        : "+f"(c[0]), "+f"(c[1]), "+f"(c[2]), "+f"(c[3])
        : "r"(a[0]), "r"(a[1]), "r"(a[2]), "r"(a[3]), "r"(b[0]), "r"(b[1]));
}

// ---------------------------------------------------------------------------
// Kernel 1: LayerNorm. One block per (b,n) row of 768. 256 threads.
// ---------------------------------------------------------------------------
__global__ void ln_kernel(const float* __restrict__ x,
                          const float* __restrict__ w,
                          const float* __restrict__ b) {
    int row = blockIdx.x;
    const float* xr = x + (size_t)row * DIM_N;
    int t = threadIdx.x;
    float v0 = xr[t], v1 = xr[t + 256], v2 = xr[t + 512];
    float s  = v0 + v1 + v2;
    float sq = v0 * v0 + v1 * v1 + v2 * v2;
    #pragma unroll
    for (int o = 16; o; o >>= 1) {
        s  += __shfl_xor_sync(0xffffffffu, s, o);
        sq += __shfl_xor_sync(0xffffffffu, sq, o);
    }
    __shared__ float ss[8], ssq[8];
    int wid = t >> 5, lid = t & 31;
    if (lid == 0) { ss[wid] = s; ssq[wid] = sq; }
    __syncthreads();
    if (wid == 0) {
        s = ss[lid & 7]; sq = ssq[lid & 7];
        #pragma unroll
        for (int o = 4; o; o >>= 1) {
            s  += __shfl_xor_sync(0xffffffffu, s, o);
            sq += __shfl_xor_sync(0xffffffffu, sq, o);
        }
        if (lid == 0) { ss[0] = s; ssq[0] = sq; }
    }
    __syncthreads();
    float mean = ss[0] * (1.0f / DIM_N);
    float var  = ssq[0] * (1.0f / DIM_N) - mean * mean;
    float rstd = rsqrtf(var + LN_EPS);
    float* o = g_xn + (size_t)row * DIM_N;
    int c = t;
    o[c] = (v0 - mean) * rstd * w[c] + b[c]; c += 256;
    o[c] = (v1 - mean) * rstd * w[c] + b[c]; c += 256;
    o[c] = (v2 - mean) * rstd * w[c] + b[c];
}

// ---------------------------------------------------------------------------
// Kernel 2/4: TF32 tensor-core GEMM  C[M,J] = A[M,K] @ W[J,K]^T + bias[J]
// ---------------------------------------------------------------------------
__global__ void __launch_bounds__(256)
tgemm_bias(const float* __restrict__ A, const float* __restrict__ W,
           const float* __restrict__ bias, float* __restrict__ C,
           int M, int J, int K) {
    __shared__ float Ash[128 * TS];
    __shared__ float Wsh[128 * TS];
    int m0 = blockIdx.y * 128;
    int j0 = blockIdx.x * 128;
    int tid = threadIdx.x;
    int warp = tid >> 5, lane = tid & 31;
    int gid = lane >> 2, tig = lane & 3;
    int wm = (warp >> 2) * 64;
    int wn = (warp & 3) * 32;
    int lr = tid >> 1;
    int lc = (tid & 1) * 16;

    const float* Ap = A + (size_t)(m0 + lr) * K + lc;
    const float* Wp = W + (size_t)(j0 + lr) * K + lc;

    float acc[4][4][4];
    #pragma unroll
    for (int mt = 0; mt < 4; mt++)
        #pragma unroll
        for (int nt = 0; nt < 4; nt++)
            #pragma unroll
            for (int e = 0; e < 4; e++) acc[mt][nt][e] = 0.0f;

    float4 pa[4], pw[4];
    #pragma unroll
    for (int c = 0; c < 4; c++) {
        pa[c] = *(const float4*)(Ap + 4 * c);
        pw[c] = *(const float4*)(Wp + 4 * c);
    }

    for (int k0 = 0; k0 < K; k0 += 32) {
        float* As = &Ash[lr * TS + lc];
        float* Ws = &Wsh[lr * TS + lc];
        #pragma unroll
        for (int c = 0; c < 4; c++) {
            As[4 * c + 0] = t32(pa[c].x); As[4 * c + 1] = t32(pa[c].y);
            As[4 * c + 2] = t32(pa[c].z); As[4 * c + 3] = t32(pa[c].w);
            Ws[4 * c + 0] = t32(pw[c].x); Ws[4 * c + 1] = t32(pw[c].y);
            Ws[4 * c + 2] = t32(pw[c].z); Ws[4 * c + 3] = t32(pw[c].w);
        }
        __syncthreads();
        if (k0 + 32 < K) {
            #pragma unroll
            for (int c = 0; c < 4; c++) {
                pa[c] = *(const float4*)(Ap + k0 + 32 + 4 * c);
                pw[c] = *(const float4*)(Wp + k0 + 32 + 4 * c);
            }
        }
        const uint32_t* Au = (const uint32_t*)Ash;
        const uint32_t* Wu = (const uint32_t*)Wsh;
        #pragma unroll
        for (int ks = 0; ks < 4; ks++) {
            uint32_t af[4][4], bf[4][2];
            #pragma unroll
            for (int mt = 0; mt < 4; mt++) {
                int r = (wm + mt * 16 + gid) * TS + ks * 8 + tig;
                af[mt][0] = Au[r];
                af[mt][1] = Au[r + 8 * TS];
                af[mt][2] = Au[r + 4];
                af[mt][3] = Au[r + 8 * TS + 4];
            }
            #pragma unroll
            for (int nt = 0; nt < 4; nt++) {
                int r = (wn + nt * 8 + gid) * TS + ks * 8 + tig;
                bf[nt][0] = Wu[r];
                bf[nt][1] = Wu[r + 4];
            }
            #pragma unroll
            for (int mt = 0; mt < 4; mt++)
                #pragma unroll
                for (int nt = 0; nt < 4; nt++)
                    mma_tf32(acc[mt][nt], af[mt], bf[nt]);
        }
        __syncthreads();
    }

    #pragma unroll
    for (int mt = 0; mt < 4; mt++) {
        int row0 = m0 + wm + mt * 16 + gid;
        #pragma unroll
        for (int nt = 0; nt < 4; nt++) {
            int col = j0 + wn + nt * 8 + tig * 2;
            float b0 = bias[col], b1 = bias[col + 1];
            float2 v0 = make_float2(acc[mt][nt][0] + b0, acc[mt][nt][1] + b1);
            float2 v1 = make_float2(acc[mt][nt][2] + b0, acc[mt][nt][3] + b1);
            *(float2*)&C[(size_t)row0 * J + col] = v0;
            *(float2*)&C[(size_t)(row0 + 8) * J + col] = v1;
        }
    }
}

// ---------------------------------------------------------------------------
// Kernel 3: fused flash attention on TF32 tensor cores.
// Block = (64-query tile, head, batch). 128 threads = 4 warps.
// Each warp: 16 query rows x 64 keys (S) and x 64 dims (O).
// smem: q[64][68], k[64][68], vT[64][68], p[64][68], bias[1024] = 73728 B.
// ---------------------------------------------------------------------------
__global__ void __launch_bounds__(128)
attn_mma_kernel(const float* __restrict__ biases) {
    extern __shared__ float sm[];
    float* q_s  = sm;                 // 64*ST
    float* k_s  = q_s + 64 * ST;
    float* vt_s = k_s + 64 * ST;      // transposed: [dim][key]
    float* p_s  = vt_s + 64 * ST;
    float* b_s  = p_s + 64 * ST;      // 1024

    int qt = blockIdx.x, h = blockIdx.y, b = blockIdx.z;
    int tid = threadIdx.x;
    int warp = tid >> 5, lane = tid & 31;
    int gid = lane >> 2, tig = lane & 3;
    int n0 = qt * 64;

    for (int i = tid; i < 1024; i += 128) b_s[i] = biases[h * 1024 + i];

    // Load Q tile [64 rows][64 dims] (tf32-rounded)
    {
        int r = tid >> 1, c0 = (tid & 1) * 32;
        const float* qp = g_qkv + (size_t)(b * N_TOK + n0 + r) * QKVD
                          + h * 192 + c0;
        float* qs = q_s + r * ST + c0;
        #pragma unroll
        for (int c = 0; c < 32; c += 4) {
            float4 v = *(const float4*)(qp + c);
            qs[c + 0] = t32(v.x); qs[c + 1] = t32(v.y);
            qs[c + 2] = t32(v.z); qs[c + 3] = t32(v.w);
        }
    }

    float oacc[8][4];
    #pragma unroll
    for (int nt = 0; nt < 8; nt++)
        #pragma unroll
        for (int e = 0; e < 4; e++) oacc[nt][e] = 0.0f;
    float m0r = -1e30f, m1r = -1e30f, l0r = 0.0f, l1r = 0.0f;

    int q0 = n0 + warp * 16 + gid, q1 = q0 + 8;
    int yq0 = q0 >> 5, xq0 = q0 & 31;
    int yq1 = q1 >> 5, xq1 = q1 & 31;
    int arow = (warp * 16 + gid) * ST;

    for (int kt = 0; kt < 16; kt++) {
        // Load K tile and V tile (V transposed into vt_s)
        {
            int r = tid >> 1, c0 = (tid & 1) * 32;
            const float* kp = g_qkv + (size_t)(b * N_TOK + kt * 64 + r) * QKVD
                              + h * 192 + 64 + c0;
            const float* vp = kp + 64;
            float* ks = k_s + r * ST + c0;
            #pragma unroll
            for (int c = 0; c < 32; c += 4) {
                float4 kv = *(const float4*)(kp + c);
                ks[c + 0] = t32(kv.x); ks[c + 1] = t32(kv.y);
                ks[c + 2] = t32(kv.z); ks[c + 3] = t32(kv.w);
                float4 vv = *(const float4*)(vp + c);
                vt_s[(c0 + c + 0) * ST + r] = t32(vv.x);
                vt_s[(c0 + c + 1) * ST + r] = t32(vv.y);
                vt_s[(c0 + c + 2) * ST + r] = t32(vv.z);
                vt_s[(c0 + c + 3) * ST + r] = t32(vv.w);
            }
        }
        __syncthreads();

        // S = Q @ K^T  (C frags: rows gid/gid+8, cols 2*tig per n-tile)
        float sacc[8][4];
        #pragma unroll
        for (int nt = 0; nt < 8; nt++)
            #pragma unroll
            for (int e = 0; e < 4; e++) sacc[nt][e] = 0.0f;
        const uint32_t* Qu = (const uint32_t*)q_s;
        const uint32_t* Ku = (const uint32_t*)k_s;
        #pragma unroll
        for (int ks = 0; ks < 8; ks++) {
            uint32_t af[4];
            int ar = arow + ks * 8 + tig;
            af[0] = Qu[ar];          af[1] = Qu[ar + 8 * ST];
            af[2] = Qu[ar + 4];      af[3] = Qu[ar + 8 * ST + 4];
            #pragma unroll
            for (int nt = 0; nt < 8; nt++) {
                uint32_t bf[2];
                int br = (nt * 8 + gid) * ST + ks * 8 + tig;
                bf[0] = Ku[br]; bf[1] = Ku[br + 4];
                mma_tf32(sacc[nt], af, bf);
            }
        }

        // scale + analytic relative-position bias, row max
        float px0 = -1e30f, px1 = -1e30f;
        #pragma unroll
        for (int nt = 0; nt < 8; nt++) {
            #pragma unroll
            for (int e = 0; e < 2; e++) {
                int key = kt * 64 + nt * 8 + tig * 2 + e;
                int ym = key >> 5, xm = key & 31;
                float bv0 = b_s[abs(yq0 - ym) * 32 + abs(xq0 - xm)];
                float bv1 = b_s[abs(yq1 - ym) * 32 + abs(xq1 - xm)];
                sacc[nt][e]     = sacc[nt][e]     * SCALE_C + bv0;
                sacc[nt][e + 2] = sacc[nt][e + 2] * SCALE_C + bv1;
                px0 = fmaxf(px0, sacc[nt][e]);
                px1 = fmaxf(px1, sacc[nt][e + 2]);
            }
        }
        px0 = fmaxf(px0, __shfl_xor_sync(0xffffffffu, px0, 1));
        px0 = fmaxf(px0, __shfl_xor_sync(0xffffffffu, px0, 2));
        px1 = fmaxf(px1, __shfl_xor_sync(0xffffffffu, px1, 1));
        px1 = fmaxf(px1, __shfl_xor_sync(0xffffffffu, px1, 2));

        float mn0 = fmaxf(m0r, px0), mn1 = fmaxf(m1r, px1);
        float cr0 = __expf(m0r - mn0), cr1 = __expf(m1r - mn1);
        float s0 = 0.0f, s1 = 0.0f;
        #pragma unroll
        for (int nt = 0; nt < 8; nt++) {
            #pragma unroll
            for (int e = 0; e < 2; e++) {
                float p0 = __expf(sacc[nt][e] - mn0);
                float p1 = __expf(sacc[nt][e + 2] - mn1);
                s0 += p0; s1 += p1;
                sacc[nt][e] = p0; sacc[nt][e + 2] = p1;
            }
        }
        s0 += __shfl_xor_sync(0xffffffffu, s0, 1);
        s0 += __shfl_xor_sync(0xffffffffu, s0, 2);
        s1 += __shfl_xor_sync(0xffffffffu, s1, 1);
        s1 += __shfl_xor_sync(0xffffffffu, s1, 2);
        l0r = l0r * cr0 + s0; m0r = mn0;
        l1r = l1r * cr1 + s1; m1r = mn1;
        #pragma unroll
        for (int nt = 0; nt < 8; nt++) {
            oacc[nt][0] *= cr0; oacc[nt][1] *= cr0;
            oacc[nt][2] *= cr1; oacc[nt][3] *= cr1;
        }

        // P: C-frag layout -> warp-private smem slab (A-frag re-gather)
        #pragma unroll
        for (int nt = 0; nt < 8; nt++) {
            int pr = arow + nt * 8 + tig * 2;
            p_s[pr]     = t32(sacc[nt][0]);
            p_s[pr + 1] = t32(sacc[nt][1]);
            p_s[pr + 8 * ST]     = t32(sacc[nt][2]);
            p_s[pr + 8 * ST + 1] = t32(sacc[nt][3]);
        }
        __syncwarp();

        // O += P @ V  (B from vT: [dim][key] col-major)
        const uint32_t* Pu = (const uint32_t*)p_s;
        const uint32_t* Vu = (const uint32_t*)vt_s;
        #pragma unroll
        for (int ks = 0; ks < 8; ks++) {
            uint32_t af[4];
            int ar = arow + ks * 8 + tig;
            af[0] = Pu[ar];          af[1] = Pu[ar + 8 * ST];
            af[2] = Pu[ar + 4];      af[3] = Pu[ar + 8 * ST + 4];
            #pragma unroll
            for (int nt = 0; nt < 8; nt++) {
                uint32_t bf[2];
                int br = (nt * 8 + gid) * ST + ks * 8 + tig;
                bf[0] = Vu[br]; bf[1] = Vu[br + 4];
                mma_tf32(oacc[nt], af, bf);
            }
        }
        __syncthreads();
    }

    // Epilogue: normalize and store
    float inv0 = 1.0f / l0r, inv1 = 1.0f / l1r;
    size_t row0 = (size_t)(b * N_TOK + n0 + warp * 16 + gid) * DIM_N;
    size_t row1 = row0 + 8 * DIM_N;
    #pragma unroll
    for (int nt = 0; nt < 8; nt++) {
        int col = h * 64 + nt * 8 + tig * 2;
        *(float2*)&g_att[row0 + col] =
            make_float2(oacc[nt][0] * inv0, oacc[nt][1] * inv0);
        *(float2*)&g_att[row1 + col] =
            make_float2(oacc[nt][2] * inv1, oacc[nt][3] * inv1);
    }
}

// ---------------------------------------------------------------------------
extern "C" void kernel_launch(void* const* d_in, const int* in_sizes, int n_in,
                              void* d_out, int out_size) {
    const float* x           = (const float*)d_in[0];
    const float* ln_w        = (const float*)d_in[1];
    const float* ln_b        = (const float*)d_in[2];
    const float* qkv_w       = (const float*)d_in[3];
    const float* qkv_b       = (const float*)d_in[4];
    const float* proj_w      = (const float*)d_in[5];
    const float* proj_b      = (const float*)d_in[6];
    const float* attn_biases = (const float*)d_in[7];
    float* out = (float*)d_out;

    void *p_xn, *p_qkv, *p_att;
    cudaGetSymbolAddress(&p_xn, g_xn);
    cudaGetSymbolAddress(&p_qkv, g_qkv);
    cudaGetSymbolAddress(&p_att, g_att);

    const int ATTN_SMEM = (4 * 64 * ST + 1024) * 4; // 73728 B
    cudaFuncSetAttribute(attn_mma_kernel,
                         cudaFuncAttributeMaxDynamicSharedMemorySize, ATTN_SMEM);

    // 1. LayerNorm
    ln_kernel<<<MROWS, 256>>>(x, ln_w, ln_b);

    // 2. QKV GEMM (TF32): [16384,768] @ [2304,768]^T
    tgemm_bias<<<dim3(QKVD / 128, MROWS / 128), 256>>>(
        (const float*)p_xn, qkv_w, qkv_b, (float*)p_qkv, MROWS, QKVD, DIM_N);

    // 3. Fused attention (TF32 tensor cores)
    attn_mma_kernel<<<dim3(N_TOK / 64, H_N, B_N), 128, ATTN_SMEM>>>(attn_biases);

    // 4. Projection GEMM (TF32): [16384,768] @ [768,768]^T
    tgemm_bias<<<dim3(DIM_N / 128, MROWS / 128), 256>>>(
        (const float*)p_att, proj_w, proj_b, out, MROWS, DIM_N, DIM_N);
}

// round 4
// speedup vs baseline: 5.5342x; 2.6740x over previous
#include <cuda_runtime.h>
#include <cuda_fp16.h>
#include <math.h>
#include <stdint.h>

// Problem constants
#define B_N   16
#define N_TOK 1024
#define DIM_N 768
#define H_N   12
#define QKVD  2304
#define MROWS 16384
#define SCALE_C 0.125f
#define LN_EPS  1e-5f

// Scratch (device globals — no dynamic allocation allowed). All fp16.
__device__ __half g_xn[(size_t)MROWS * DIM_N];
__device__ __half g_qkv[(size_t)MROWS * QKVD];
__device__ __half g_att[(size_t)MROWS * DIM_N];
__device__ __half g_wq[(size_t)QKVD * DIM_N];
__device__ __half g_wp[(size_t)DIM_N * DIM_N];

// ---------------------------------------------------------------------------
// PTX helpers
// ---------------------------------------------------------------------------
__device__ __forceinline__ uint32_t sptr(const void* p) {
    return (uint32_t)__cvta_generic_to_shared(p);
}
__device__ __forceinline__ void ldmx4(uint32_t* r, uint32_t a) {
    asm volatile("ldmatrix.sync.aligned.m8n8.x4.shared.b16 {%0,%1,%2,%3}, [%4];"
                 : "=r"(r[0]), "=r"(r[1]), "=r"(r[2]), "=r"(r[3]) : "r"(a));
}
__device__ __forceinline__ void ldmx4t(uint32_t* r, uint32_t a) {
    asm volatile("ldmatrix.sync.aligned.m8n8.x4.trans.shared.b16 {%0,%1,%2,%3}, [%4];"
                 : "=r"(r[0]), "=r"(r[1]), "=r"(r[2]), "=r"(r[3]) : "r"(a));
}
__device__ __forceinline__ void mma16816(float* c, const uint32_t* a,
                                         uint32_t b0, uint32_t b1) {
    asm volatile(
        "mma.sync.aligned.m16n8k16.row.col.f32.f16.f16.f32 "
        "{%0,%1,%2,%3}, {%4,%5,%6,%7}, {%8,%9}, {%0,%1,%2,%3};"
        : "+f"(c[0]), "+f"(c[1]), "+f"(c[2]), "+f"(c[3])
        : "r"(a[0]), "r"(a[1]), "r"(a[2]), "r"(a[3]), "r"(b0), "r"(b1));
}
__device__ __forceinline__ uint32_t packh2(float x, float y) {
    __half2 h = __floats2half2_rn(x, y);
    return *(uint32_t*)&h;
}
#define CP_ASYNC(dst, src) \
    asm volatile("cp.async.cg.shared.global [%0], [%1], 16;" :: "r"(dst), "l"(src))
#define CP_COMMIT() asm volatile("cp.async.commit_group;")
#define CP_WAIT0()  asm volatile("cp.async.wait_group 0;")
#define CP_WAIT1()  asm volatile("cp.async.wait_group 1;")

// ---------------------------------------------------------------------------
// Kernel 0: fp32 -> fp16 weight conversion
// ---------------------------------------------------------------------------
__global__ void cvt_f2h(const float* __restrict__ s, __half* __restrict__ d,
                        int n) {
    int i = (blockIdx.x * 256 + threadIdx.x) * 4;
    if (i < n) {
        float4 v = *(const float4*)(s + i);
        *(__half2*)(d + i)     = __floats2half2_rn(v.x, v.y);
        *(__half2*)(d + i + 2) = __floats2half2_rn(v.z, v.w);
    }
}

// ---------------------------------------------------------------------------
// Kernel 1: LayerNorm -> fp16 output. One block per row. 256 threads.
// ---------------------------------------------------------------------------
__global__ void ln_kernel(const float* __restrict__ x,
                          const float* __restrict__ w,
                          const float* __restrict__ b) {
    int row = blockIdx.x;
    const float* xr = x + (size_t)row * DIM_N;
    int t = threadIdx.x;
    float v0 = xr[t], v1 = xr[t + 256], v2 = xr[t + 512];
    float s  = v0 + v1 + v2;
    float sq = v0 * v0 + v1 * v1 + v2 * v2;
    #pragma unroll
    for (int o = 16; o; o >>= 1) {
        s  += __shfl_xor_sync(0xffffffffu, s, o);
        sq += __shfl_xor_sync(0xffffffffu, sq, o);
    }
    __shared__ float ss[8], ssq[8];
    int wid = t >> 5, lid = t & 31;
    if (lid == 0) { ss[wid] = s; ssq[wid] = sq; }
    __syncthreads();
    if (wid == 0) {
        s = ss[lid & 7]; sq = ssq[lid & 7];
        #pragma unroll
        for (int o = 4; o; o >>= 1) {
            s  += __shfl_xor_sync(0xffffffffu, s, o);
            sq += __shfl_xor_sync(0xffffffffu, sq, o);
        }
        if (lid == 0) { ss[0] = s; ssq[0] = sq; }
    }
    __syncthreads();
    float mean = ss[0] * (1.0f / DIM_N);
    float var  = ssq[0] * (1.0f / DIM_N) - mean * mean;
    float rstd = rsqrtf(var + LN_EPS);
    __half* o = g_xn + (size_t)row * DIM_N;
    int c = t;
    o[c] = __float2half((v0 - mean) * rstd * w[c] + b[c]); c += 256;
    o[c] = __float2half((v1 - mean) * rstd * w[c] + b[c]); c += 256;
    o[c] = __float2half((v2 - mean) * rstd * w[c] + b[c]);
}

// ---------------------------------------------------------------------------
// Kernel 2/4: fp16 tensor-core GEMM  C[M,J] = A[M,K] @ W[J,K]^T + bias[J]
// 128x128 tile, BK=64, 8 warps (2x4), warp 64x32, mma.m16n8k16.
// cp.async 2-stage pipeline, XOR-swizzled smem, ldmatrix fragment loads.
// ---------------------------------------------------------------------------
template <int OUT_HALF>
__global__ void __launch_bounds__(256, 2)
hgemm_bias(const __half* __restrict__ A, const __half* __restrict__ W,
           const float* __restrict__ bias, void* __restrict__ Cv,
           int M, int J, int K) {
    extern __shared__ __half smh[];
    // layout (halfs): A0[8192] A1[8192] W0[8192] W1[8192]
    __half* Abuf[2] = { smh, smh + 8192 };
    __half* Wbuf[2] = { smh + 16384, smh + 24576 };

    int m0 = blockIdx.y * 128, j0 = blockIdx.x * 128;
    int tid = threadIdx.x, warp = tid >> 5, lane = tid & 31;
    int gid = lane >> 2, tig = lane & 3;
    int wm = (warp >> 2) * 64, wn = (warp & 3) * 32;
    int lr = tid >> 1, side = tid & 1;

    const __half* Ap = A + (size_t)(m0 + lr) * K + side * 32;
    const __half* Wp = W + (size_t)(j0 + lr) * K + side * 32;

    int soff[4];
    #pragma unroll
    for (int j = 0; j < 4; j++) {
        int c = side * 4 + j;
        soff[j] = lr * 64 + ((c ^ (lr & 7)) * 8);
    }

    int tile = lane >> 3, rlow = lane & 7;
    int rowin = (tile & 1) * 8 + rlow;   // row within a 16-row frag tile
    int chsel = tile >> 1;               // k-chunk within k16

    float acc[4][4][4];
    #pragma unroll
    for (int mt = 0; mt < 4; mt++)
        #pragma unroll
        for (int nt = 0; nt < 4; nt++)
            #pragma unroll
            for (int e = 0; e < 4; e++) acc[mt][nt][e] = 0.0f;

    int nk = K / 64;
    // prologue: stage 0
    #pragma unroll
    for (int j = 0; j < 4; j++) {
        CP_ASYNC(sptr(&Abuf[0][soff[j]]), Ap + 8 * j);
        CP_ASYNC(sptr(&Wbuf[0][soff[j]]), Wp + 8 * j);
    }
    CP_COMMIT();

    for (int i = 0; i < nk; i++) {
        int cur = i & 1;
        if (i + 1 < nk) {
            int nxt = cur ^ 1;
            const __half* Ai = Ap + (i + 1) * 64;
            const __half* Wi = Wp + (i + 1) * 64;
            #pragma unroll
            for (int j = 0; j < 4; j++) {
                CP_ASYNC(sptr(&Abuf[nxt][soff[j]]), Ai + 8 * j);
                CP_ASYNC(sptr(&Wbuf[nxt][soff[j]]), Wi + 8 * j);
            }
            CP_COMMIT();
            CP_WAIT1();
        } else {
            CP_WAIT0();
        }
        __syncthreads();

        uint32_t Ab = sptr(Abuf[cur]), Wb = sptr(Wbuf[cur]);
        #pragma unroll
        for (int ks = 0; ks < 4; ks++) {
            int chunk = ((2 * ks + chsel) ^ rlow) * 8;
            uint32_t af[4][4];
            #pragma unroll
            for (int mt = 0; mt < 4; mt++)
                ldmx4(af[mt], Ab + ((wm + mt * 16 + rowin) * 64 + chunk) * 2);
            #pragma unroll
            for (int g = 0; g < 2; g++) {
                uint32_t r4[4];
                ldmx4(r4, Wb + ((wn + g * 16 + rowin) * 64 + chunk) * 2);
                #pragma unroll
                for (int mt = 0; mt < 4; mt++) {
                    mma16816(acc[mt][2 * g],     af[mt], r4[0], r4[2]);
                    mma16816(acc[mt][2 * g + 1], af[mt], r4[1], r4[3]);
                }
            }
        }
        __syncthreads();
    }

    // Epilogue
    #pragma unroll
    for (int mt = 0; mt < 4; mt++) {
        int row0 = m0 + wm + mt * 16 + gid;
        #pragma unroll
        for (int nt = 0; nt < 4; nt++) {
            int col = j0 + wn + nt * 8 + tig * 2;
            float b0 = bias[col], b1 = bias[col + 1];
            if (OUT_HALF) {
                __half* C = (__half*)Cv;
                *(uint32_t*)&C[(size_t)row0 * J + col] =
                    packh2(acc[mt][nt][0] + b0, acc[mt][nt][1] + b1);
                *(uint32_t*)&C[(size_t)(row0 + 8) * J + col] =
                    packh2(acc[mt][nt][2] + b0, acc[mt][nt][3] + b1);
            } else {
                float* C = (float*)Cv;
                *(float2*)&C[(size_t)row0 * J + col] =
                    make_float2(acc[mt][nt][0] + b0, acc[mt][nt][1] + b1);
                *(float2*)&C[(size_t)(row0 + 8) * J + col] =
                    make_float2(acc[mt][nt][2] + b0, acc[mt][nt][3] + b1);
            }
        }
    }
}

// ---------------------------------------------------------------------------
// Kernel 3: fused flash attention, fp16 MMA (m16n8k16).
// Block = (128-query tile, head, batch). 256 threads = 8 warps, 16 q-rows each.
// Q staged once (swizzled); per 64-key tile: K/V staged, S via ldmatrix+MMA,
// register softmax, P repacked in registers (no smem), PV via ldmatrix.trans.
// ---------------------------------------------------------------------------
__global__ void __launch_bounds__(256, 2)
attn_kernel(const float* __restrict__ biases) {
    __shared__ __half Qs[128 * 64];
    __shared__ __half Ks[64 * 64];
    __shared__ __half Vs[64 * 64];
    __shared__ float  b_s[1024];

    int qt = blockIdx.x, h = blockIdx.y, b = blockIdx.z;
    int tid = threadIdx.x, warp = tid >> 5, lane = tid & 31;
    int gid = lane >> 2, tig = lane & 3;
    int n0 = qt * 128;

    for (int i = tid; i < 1024; i += 256) b_s[i] = biases[h * 1024 + i];

    // Stage Q [128 rows][64 dims], swizzled
    {
        int r = tid >> 1, side = tid & 1;
        const __half* qp = g_qkv + (size_t)(b * N_TOK + n0 + r) * QKVD
                           + h * 192 + side * 32;
        #pragma unroll
        for (int j = 0; j < 4; j++) {
            int c = side * 4 + j;
            *(uint4*)&Qs[r * 64 + ((c ^ (r & 7)) * 8)] =
                *(const uint4*)(qp + 8 * j);
        }
    }

    int tile = lane >> 3, rlow = lane & 7;
    int rowin = (tile & 1) * 8 + rlow;
    int chsel = tile >> 1;
    uint32_t Qb = sptr(Qs), Kb = sptr(Ks), Vb = sptr(Vs);

    float oacc[8][4];
    #pragma unroll
    for (int nt = 0; nt < 8; nt++)
        #pragma unroll
        for (int e = 0; e < 4; e++) oacc[nt][e] = 0.0f;
    float m0r = -1e30f, m1r = -1e30f, l0r = 0.0f, l1r = 0.0f;

    int q0 = n0 + warp * 16 + gid, q1 = q0 + 8;
    int yq0 = q0 >> 5, xq0 = q0 & 31;
    int yq1 = q1 >> 5, xq1 = q1 & 31;

    for (int kt = 0; kt < 16; kt++) {
        // Stage K, V tiles [64][64], swizzled
        {
            int r = tid >> 2, q = tid & 3;
            const __half* kp = g_qkv + (size_t)(b * N_TOK + kt * 64 + r) * QKVD
                               + h * 192 + 64 + q * 16;
            const __half* vp = kp + 64;
            #pragma unroll
            for (int j = 0; j < 2; j++) {
                int c = q * 2 + j;
                int off = r * 64 + ((c ^ (r & 7)) * 8);
                *(uint4*)&Ks[off] = *(const uint4*)(kp + 8 * j);
                *(uint4*)&Vs[off] = *(const uint4*)(vp + 8 * j);
            }
        }
        __syncthreads();

        // S = Q @ K^T
        float sacc[8][4];
        #pragma unroll
        for (int nt = 0; nt < 8; nt++)
            #pragma unroll
            for (int e = 0; e < 4; e++) sacc[nt][e] = 0.0f;
        #pragma unroll
        for (int ks = 0; ks < 4; ks++) {
            int chunk = ((2 * ks + chsel) ^ rlow) * 8;
            uint32_t af[4];
            ldmx4(af, Qb + ((warp * 16 + rowin) * 64 + chunk) * 2);
            #pragma unroll
            for (int g = 0; g < 4; g++) {
                uint32_t r4[4];
                ldmx4(r4, Kb + ((g * 16 + rowin) * 64 + chunk) * 2);
                mma16816(sacc[2 * g],     af, r4[0], r4[2]);
                mma16816(sacc[2 * g + 1], af, r4[1], r4[3]);
            }
        }

        // scale + analytic relative-position bias; row max
        float px0 = -1e30f, px1 = -1e30f;
        #pragma unroll
        for (int nt = 0; nt < 8; nt++) {
            #pragma unroll
            for (int e = 0; e < 2; e++) {
                int key = kt * 64 + nt * 8 + tig * 2 + e;
                int ym = key >> 5, xm = key & 31;
                float bv0 = b_s[abs(yq0 - ym) * 32 + abs(xq0 - xm)];
                float bv1 = b_s[abs(yq1 - ym) * 32 + abs(xq1 - xm)];
                sacc[nt][e]     = sacc[nt][e]     * SCALE_C + bv0;
                sacc[nt][e + 2] = sacc[nt][e + 2] * SCALE_C + bv1;
                px0 = fmaxf(px0, sacc[nt][e]);
                px1 = fmaxf(px1, sacc[nt][e + 2]);
            }
        }
        px0 = fmaxf(px0, __shfl_xor_sync(0xffffffffu, px0, 1));
        px0 = fmaxf(px0, __shfl_xor_sync(0xffffffffu, px0, 2));
        px1 = fmaxf(px1, __shfl_xor_sync(0xffffffffu, px1, 1));
        px1 = fmaxf(px1, __shfl_xor_sync(0xffffffffu, px1, 2));

        float mn0 = fmaxf(m0r, px0), mn1 = fmaxf(m1r, px1);
        float cr0 = __expf(m0r - mn0), cr1 = __expf(m1r - mn1);
        float s0 = 0.0f, s1 = 0.0f;
        #pragma unroll
        for (int nt = 0; nt < 8; nt++) {
            #pragma unroll
            for (int e = 0; e < 2; e++) {
                float p0 = __expf(sacc[nt][e] - mn0);
                float p1 = __expf(sacc[nt][e + 2] - mn1);
                s0 += p0; s1 += p1;
                sacc[nt][e] = p0; sacc[nt][e + 2] = p1;
            }
        }
        s0 += __shfl_xor_sync(0xffffffffu, s0, 1);
        s0 += __shfl_xor_sync(0xffffffffu, s0, 2);
        s1 += __shfl_xor_sync(0xffffffffu, s1, 1);
        s1 += __shfl_xor_sync(0xffffffffu, s1, 2);
        l0r = l0r * cr0 + s0; m0r = mn0;
        l1r = l1r * cr1 + s1; m1r = mn1;
        #pragma unroll
        for (int nt = 0; nt < 8; nt++) {
            oacc[nt][0] *= cr0; oacc[nt][1] *= cr0;
            oacc[nt][2] *= cr1; oacc[nt][3] *= cr1;
        }

        // O += P @ V : P repacked from S C-frags into A-frags in registers
        #pragma unroll
        for (int c = 0; c < 4; c++) {
            uint32_t pa[4];
            pa[0] = packh2(sacc[2 * c][0],     sacc[2 * c][1]);
            pa[1] = packh2(sacc[2 * c][2],     sacc[2 * c][3]);
            pa[2] = packh2(sacc[2 * c + 1][0], sacc[2 * c + 1][1]);
            pa[3] = packh2(sacc[2 * c + 1][2], sacc[2 * c + 1][3]);
            #pragma unroll
            for (int g = 0; g < 4; g++) {
                uint32_t r4[4];
                int row = c * 16 + rowin;
                ldmx4t(r4, Vb + (row * 64 + (((2 * g + chsel) ^ (row & 7)) * 8)) * 2);
                mma16816(oacc[2 * g],     pa, r4[0], r4[1]);
                mma16816(oacc[2 * g + 1], pa, r4[2], r4[3]);
            }
        }
        __syncthreads();
    }

    // Epilogue: normalize and store fp16
    float inv0 = 1.0f / l0r, inv1 = 1.0f / l1r;
    size_t row0 = (size_t)(b * N_TOK + n0 + warp * 16 + gid) * DIM_N;
    size_t row1 = row0 + 8 * DIM_N;
    #pragma unroll
    for (int nt = 0; nt < 8; nt++) {
        int col = h * 64 + nt * 8 + tig * 2;
        *(uint32_t*)&g_att[row0 + col] =
            packh2(oacc[nt][0] * inv0, oacc[nt][1] * inv0);
        *(uint32_t*)&g_att[row1 + col] =
            packh2(oacc[nt][2] * inv1, oacc[nt][3] * inv1);
    }
}

// ---------------------------------------------------------------------------
extern "C" void kernel_launch(void* const* d_in, const int* in_sizes, int n_in,
                              void* d_out, int out_size) {
    const float* x           = (const float*)d_in[0];
    const float* ln_w        = (const float*)d_in[1];
    const float* ln_b        = (const float*)d_in[2];
    const float* qkv_w       = (const float*)d_in[3];
    const float* qkv_b       = (const float*)d_in[4];
    const float* proj_w      = (const float*)d_in[5];
    const float* proj_b      = (const float*)d_in[6];
    const float* attn_biases = (const float*)d_in[7];
    float* out = (float*)d_out;

    void *p_xn, *p_qkv, *p_att, *p_wq, *p_wp;
    cudaGetSymbolAddress(&p_xn, g_xn);
    cudaGetSymbolAddress(&p_qkv, g_qkv);
    cudaGetSymbolAddress(&p_att, g_att);
    cudaGetSymbolAddress(&p_wq, g_wq);
    cudaGetSymbolAddress(&p_wp, g_wp);

    const int GEMM_SMEM = 32768 * 2; // 64 KB
    cudaFuncSetAttribute(hgemm_bias<1>,
                         cudaFuncAttributeMaxDynamicSharedMemorySize, GEMM_SMEM);
    cudaFuncSetAttribute(hgemm_bias<0>,
                         cudaFuncAttributeMaxDynamicSharedMemorySize, GEMM_SMEM);

    // 0. Weight conversion fp32 -> fp16
    cvt_f2h<<<(QKVD * DIM_N / 4 + 255) / 256, 256>>>(qkv_w, (__half*)p_wq,
                                                     QKVD * DIM_N);
    cvt_f2h<<<(DIM_N * DIM_N / 4 + 255) / 256, 256>>>(proj_w, (__half*)p_wp,
                                                      DIM_N * DIM_N);

    // 1. LayerNorm -> fp16
    ln_kernel<<<MROWS, 256>>>(x, ln_w, ln_b);

    // 2. QKV GEMM (fp16 HMMA): [16384,768] @ [2304,768]^T -> fp16
    hgemm_bias<1><<<dim3(QKVD / 128, MROWS / 128), 256, GEMM_SMEM>>>(
        (const __half*)p_xn, (const __half*)p_wq, qkv_b, p_qkv,
        MROWS, QKVD, DIM_N);

    // 3. Fused attention (fp16 HMMA)
    attn_kernel<<<dim3(N_TOK / 128, H_N, B_N), 256>>>(attn_biases);

    // 4. Projection GEMM (fp16 HMMA) -> fp32 output
    hgemm_bias<0><<<dim3(DIM_N / 128, MROWS / 128), 256, GEMM_SMEM>>>(
        (const __half*)p_att, (const __half*)p_wp, proj_b, d_out,
        MROWS, DIM_N, DIM_N);
}